// round 13
// baseline (speedup 1.0000x reference)
#include <cuda_runtime.h>

// Problem constants (match reference_code)
#define B_    256
#define PER_  1024
#define NIN_  256
#define NOUT_ (PER_ - NIN_)
#define K_    32
#define E_    (B_ * NIN_ * K_)      // 2,097,152

#define TPB_  512
#define WPB_  16                     // warps per block
#define TGT_PER_BLOCK 32             // 2 targets per warp
#define BPB_  (NIN_ / TGT_PER_BLOCK) // 8 blocks per batch
#define GRID_ (B_ * BPB_)            // 2048

typedef unsigned long long u64;

// ---- packed f32x2 helpers ----
__device__ __forceinline__ u64 pack2(float lo, float hi) {
    u64 r; asm("mov.b64 %0, {%1, %2};" : "=l"(r) : "f"(lo), "f"(hi)); return r;
}
__device__ __forceinline__ void unpack2(u64 v, float& lo, float& hi) {
    asm("mov.b64 {%0, %1}, %2;" : "=f"(lo), "=f"(hi) : "l"(v));
}
__device__ __forceinline__ u64 add2(u64 a, u64 b) {
    u64 r; asm("add.rn.f32x2 %0, %1, %2;" : "=l"(r) : "l"(a), "l"(b)); return r;
}
__device__ __forceinline__ u64 mul2(u64 a, u64 b) {
    u64 r; asm("mul.rn.f32x2 %0, %1, %2;" : "=l"(r) : "l"(a), "l"(b)); return r;
}
__device__ __forceinline__ u64 fma2(u64 a, u64 b, u64 c) {
    u64 r; asm("fma.rn.f32x2 %0, %1, %2, %3;" : "=l"(r) : "l"(a), "l"(b), "l"(c)); return r;
}
__device__ __forceinline__ float sqrt_approx(float x) {
    float r; asm("sqrt.approx.f32 %0, %1;" : "=f"(r) : "f"(x)); return r;
}

// Quad-packed smem layout: float index of candidate j (bit permutation):
//   fidx = ((j>>7)<<7) | ((j&31)<<2) | ((j>>5)&3)
__device__ __forceinline__ int fidx_of(int j) {
    return ((j >> 7) << 7) | ((j & 31) << 2) | ((j >> 5) & 3);
}

// validity: d = sqrt(d2) < 6  <=>  d2 < 36 (monotone sqrt, sqrt(36)=6 exact)

// ---- rank selection for one target (shared packed prefix scan) ----
// All __shfl_sync executed unconditionally by all 32 lanes, full mask;
// only probe acceptance is predicated (R11 divergence-fix invariant).
template<int W, int SH>
__device__ __forceinline__ void emit_one(
    unsigned mw, int packed, int incl, int cnt, int lane,
    float xi, float yi, float zi,
    const float* __restrict__ sx, const float* __restrict__ sy,
    const float* __restrict__ sz,
    int joff, int gi, int goff, int base,
    float* __restrict__ o_src, float* __restrict__ o_tgt,
    float* __restrict__ o_m,   float* __restrict__ o_d)
{
    const unsigned full = 0xffffffffu;
    bool usev = (lane < cnt);
    int r = usev ? lane : (lane - cnt);
    int lo = 0;
#pragma unroll
    for (int s = (W > 8 ? 16 : 4); s >= 1; s >>= 1) {
        int probe = lo + s;
        int src = (probe < W ? probe : W) - 1;
        int pvp = __shfl_sync(full, incl, src);
        int pv  = (pvp >> SH) & 0xffff;
        int pvu = usev ? pv : ((probe << 5) - pv);
        if (probe < W && pvu <= r) lo = probe;
    }
    int inclp = __shfl_sync(full, incl, lo);
    int pcp   = __shfl_sync(full, packed, lo);
    int incl_lo = (inclp >> SH) & 0xffff;
    int pc_lo   = (pcp  >> SH) & 0xffff;
    int excl_v  = incl_lo - pc_lo;
    int exclu   = usev ? excl_v : ((lo << 5) - excl_v);
    int rin     = r - exclu;
    unsigned mwlo = __shfl_sync(full, mw, lo);
    unsigned msel = usev ? mwlo : ~mwlo;
    int bit = __fns(msel, 0, rin + 1);
    int j = joff + (lo << 5) + bit;                      // batch-local index
    int fi = fidx_of(j);
    float dx = xi + sx[fi], dy = yi + sy[fi], dz = zi + sz[fi]; // coords negated
    float d2 = fmaf(dx, dx, fmaf(dy, dy, dz * dz));      // same chain as scan
    o_src[base] = (float)(goff + j);
    o_tgt[base] = (float)(goff + gi);
    o_m[base]   = usev ? 1.0f : 0.0f;
    o_d[base]   = usev ? sqrt_approx(d2) : 0.0f;
}

// joint A/B selection: one packed (A | B<<16) prefix scan serves both targets
template<int W>
__device__ __forceinline__ void select_pair(
    unsigned mwA, unsigned mwB, int lane,
    float xA, float yA, float zA, float xB, float yB, float zB,
    const float* __restrict__ sx, const float* __restrict__ sy,
    const float* __restrict__ sz,
    int joff, int iA, int iB, int goff, int baseA, int baseB,
    float* __restrict__ o_src, float* __restrict__ o_tgt,
    float* __restrict__ o_m,   float* __restrict__ o_d)
{
    const unsigned full = 0xffffffffu;
    int packed = __popc(mwA) | (__popc(mwB) << 16);
    int incl = packed;
#pragma unroll
    for (int d = 1; d < (W > 8 ? 32 : 8); d <<= 1) {
        int n = __shfl_up_sync(full, incl, d);
        if (lane >= d) incl += n;
    }
    int cntP = __shfl_sync(full, incl, W - 1);
    emit_one<W, 0>(mwA, packed, incl, cntP & 0xffff, lane, xA, yA, zA,
                   sx, sy, sz, joff, iA, goff, baseA, o_src, o_tgt, o_m, o_d);
    emit_one<W, 16>(mwB, packed, incl, cntP >> 16, lane, xB, yB, zB,
                    sx, sy, sz, joff, iB, goff, baseB, o_src, o_tgt, o_m, o_d);
}

__global__ void __launch_bounds__(TPB_, 3)
mo3enet_knn_ovl_kernel(const float* __restrict__ pos, float* __restrict__ out) {
    __shared__ ulonglong2 snx4[PER_ / 4];       // 4 KB  negated x, quad-packed
    __shared__ ulonglong2 sny4[PER_ / 4];       // 4 KB
    __shared__ ulonglong2 snz4[PER_ / 4];       // 4 KB
    __shared__ unsigned   smA[WPB_][32];        // 2 KB  masks, word w = cands [32w,32w+32)
    __shared__ unsigned   smB[WPB_][32];        // 2 KB

    const int b    = blockIdx.x / BPB_;
    const int grp  = blockIdx.x % BPB_;
    const int tid  = threadIdx.x;
    const int warp = tid >> 5;
    const int lane = tid & 31;
    const unsigned full = 0xffffffffu;

    const float* sx = (const float*)snx4;
    const float* sy = (const float*)sny4;
    const float* sz = (const float*)snz4;

    // ---- stage batch positions (negated) into quad-packed SoA ----
    const float* p = pos + (size_t)b * PER_ * 3;
    for (int j = tid; j < PER_; j += TPB_) {
        int fi = fidx_of(j);
        ((float*)snx4)[fi] = -p[3 * j + 0];
        ((float*)sny4)[fi] = -p[3 * j + 1];
        ((float*)snz4)[fi] = -p[3 * j + 2];
    }
    __syncthreads();

    // this warp's two targets
    const int iA = grp * TGT_PER_BLOCK + warp * 2;
    const int iB = iA + 1;
    const int goff = b * PER_;

    float xA, yA, zA, xB, yB, zB;
    {
        int fa = fidx_of(iA);
        xA = -sx[fa]; yA = -sy[fa]; zA = -sz[fa];
        int fb = fidx_of(iB);
        xB = -sx[fb]; yB = -sy[fb]; zB = -sz[fb];
    }
    const u64 xA2 = pack2(xA, xA), yA2 = pack2(yA, yA), zA2 = pack2(zA, zA);
    const u64 xB2 = pack2(xB, xB), yB2 = pack2(yB, yB), zB2 = pack2(zB, zB);

    const int baseA = (b * NIN_ + iA) * K_ + lane;
    const int baseB = (b * NIN_ + iB) * K_ + lane;

    // ---- scan macro body for one 128-candidate tile t ----
#define SCAN_TILE(t)                                                          \
    {                                                                         \
        ulonglong2 qx = snx4[(t) * 32 + lane];                                \
        ulonglong2 qy = sny4[(t) * 32 + lane];                                \
        ulonglong2 qz = snz4[(t) * 32 + lane];                                \
        {                                                                     \
            u64 dxl = add2(xA2, qx.x), dxh = add2(xA2, qx.y);                 \
            u64 dyl = add2(yA2, qy.x), dyh = add2(yA2, qy.y);                 \
            u64 dzl = add2(zA2, qz.x), dzh = add2(zA2, qz.y);                 \
            u64 sl = fma2(dxl, dxl, fma2(dyl, dyl, mul2(dzl, dzl)));          \
            u64 sh = fma2(dxh, dxh, fma2(dyh, dyh, mul2(dzh, dzh)));          \
            float f0, f1, f2, f3; unpack2(sl, f0, f1); unpack2(sh, f2, f3);   \
            uint4 m;                                                          \
            m.x = __ballot_sync(full, f0 < 36.0f);                            \
            m.y = __ballot_sync(full, f1 < 36.0f);                            \
            m.z = __ballot_sync(full, f2 < 36.0f);                            \
            m.w = __ballot_sync(full, f3 < 36.0f);                            \
            if (lane == 0) *(uint4*)&smA[warp][4 * (t)] = m;                  \
        }                                                                     \
        {                                                                     \
            u64 dxl = add2(xB2, qx.x), dxh = add2(xB2, qx.y);                 \
            u64 dyl = add2(yB2, qy.x), dyh = add2(yB2, qy.y);                 \
            u64 dzl = add2(zB2, qz.x), dzh = add2(zB2, qz.y);                 \
            u64 sl = fma2(dxl, dxl, fma2(dyl, dyl, mul2(dzl, dzl)));          \
            u64 sh = fma2(dxh, dxh, fma2(dyh, dyh, mul2(dzh, dzh)));          \
            float f0, f1, f2, f3; unpack2(sl, f0, f1); unpack2(sh, f2, f3);   \
            uint4 m;                                                          \
            m.x = __ballot_sync(full, f0 < 36.0f);                            \
            m.y = __ballot_sync(full, f1 < 36.0f);                            \
            m.z = __ballot_sync(full, f2 < 36.0f);                            \
            m.w = __ballot_sync(full, f3 < 36.0f);                            \
            if (lane == 0) *(uint4*)&smB[warp][4 * (t)] = m;                  \
        }                                                                     \
    }

    // ===== phase 1: ii tiles (candidates 0..255 = words 0..7) ================
    SCAN_TILE(0)
    SCAN_TILE(1)
    __syncwarp();

    // ===== phase 2: io scan (tiles 2..7) + ii selection, one barrier-free ====
    // region so ptxas can interleave scan math into the selection shfl gaps.
    {
        unsigned mwA = smA[warp][lane];
        unsigned mwB = smB[warp][lane];
        // clear self bit (d2(i,i)=0<36 set it); word index = i>>5 in [0,8)
        if (lane == (iA >> 5)) mwA &= ~(1u << (iA & 31));
        if (lane == (iB >> 5)) mwB &= ~(1u << (iB & 31));

        SCAN_TILE(2)
        SCAN_TILE(3)
        SCAN_TILE(4)
        SCAN_TILE(5)
        SCAN_TILE(6)
        SCAN_TILE(7)

        select_pair<NIN_ / 32>(mwA, mwB, lane, xA, yA, zA, xB, yB, zB,
                               sx, sy, sz, 0, iA, iB, goff, baseA, baseB,
                               out + 0 * E_, out + 1 * E_, out + 2 * E_, out + 3 * E_);
    }
    __syncwarp();

    // ===== phase 3: io selection (words 8..31, W=24) =========================
    {
        int wl = (8 + lane) & 31;     // lanes 24..31 wrap in-bounds (unused)
        unsigned mwA = smA[warp][wl];
        unsigned mwB = smB[warp][wl];
        select_pair<NOUT_ / 32>(mwA, mwB, lane, xA, yA, zA, xB, yB, zB,
                                sx, sy, sz, NIN_, iA, iB, goff, baseA, baseB,
                                out + 4 * E_, out + 5 * E_, out + 6 * E_, out + 7 * E_);
    }
#undef SCAN_TILE
}

extern "C" void kernel_launch(void* const* d_in, const int* in_sizes, int n_in,
                              void* d_out, int out_size) {
    const float* pos = (const float*)d_in[0];   // [N, 3] float32
    float* out = (float*)d_out;
    mo3enet_knn_ovl_kernel<<<GRID_, TPB_>>>(pos, out);
}

// round 14
// speedup vs baseline: 1.0109x; 1.0109x over previous
#include <cuda_runtime.h>

// Problem constants (match reference_code)
#define B_    256
#define PER_  1024
#define NIN_  256
#define NOUT_ (PER_ - NIN_)
#define K_    32
#define E_    (B_ * NIN_ * K_)      // 2,097,152

#define TPB_  512
#define WPB_  16                     // warps per block
#define TGT_PER_BLOCK 32             // 2 targets per warp
#define BPB_  (NIN_ / TGT_PER_BLOCK) // 8 blocks per batch
#define GRID_ (B_ * BPB_)            // 2048

typedef unsigned long long u64;

// ---- packed f32x2 helpers ----
__device__ __forceinline__ u64 pack2(float lo, float hi) {
    u64 r; asm("mov.b64 %0, {%1, %2};" : "=l"(r) : "f"(lo), "f"(hi)); return r;
}
__device__ __forceinline__ void unpack2(u64 v, float& lo, float& hi) {
    asm("mov.b64 {%0, %1}, %2;" : "=f"(lo), "=f"(hi) : "l"(v));
}
__device__ __forceinline__ u64 add2(u64 a, u64 b) {
    u64 r; asm("add.rn.f32x2 %0, %1, %2;" : "=l"(r) : "l"(a), "l"(b)); return r;
}
__device__ __forceinline__ u64 mul2(u64 a, u64 b) {
    u64 r; asm("mul.rn.f32x2 %0, %1, %2;" : "=l"(r) : "l"(a), "l"(b)); return r;
}
__device__ __forceinline__ u64 fma2(u64 a, u64 b, u64 c) {
    u64 r; asm("fma.rn.f32x2 %0, %1, %2, %3;" : "=l"(r) : "l"(a), "l"(b), "l"(c)); return r;
}
__device__ __forceinline__ float sqrt_approx(float x) {
    float r; asm("sqrt.approx.f32 %0, %1;" : "=f"(r) : "f"(x)); return r;
}

// Branchless (rin+1)-th-set-bit finder: 5-step popc binary search, ~25 fixed-lat
// ALU ops, replacing __fns (which ptxas emulates with a long sequence for
// dynamic n). Precondition: msel has at least rin+1 set bits.
__device__ __forceinline__ int nth_set_bit(unsigned m, int need /*1-based*/) {
    int pos = 0;
    int c = __popc(m & 0xffffu);
    if (c < need) { need -= c; pos = 16; }
    c = __popc((m >> pos) & 0xffu);
    if (c < need) { need -= c; pos += 8; }
    c = __popc((m >> pos) & 0xfu);
    if (c < need) { need -= c; pos += 4; }
    c = __popc((m >> pos) & 0x3u);
    if (c < need) { need -= c; pos += 2; }
    c = (m >> pos) & 1u;
    if (c < need) { pos += 1; }
    return pos;
}

// Quad-packed smem layout: float index of candidate j (bit permutation):
//   fidx = ((j>>7)<<7) | ((j&31)<<2) | ((j>>5)&3)
__device__ __forceinline__ int fidx_of(int j) {
    return ((j >> 7) << 7) | ((j & 31) << 2) | ((j >> 5) & 3);
}

// validity: d = sqrt(d2) < 6  <=>  d2 < 36 (monotone sqrt, sqrt(36)=6 exact)

// ---- rank selection for one target (shared packed prefix scan) ----
// All __shfl_sync executed unconditionally by all 32 lanes, full mask;
// only probe acceptance is predicated (R11 divergence-fix invariant).
template<int W, int SH>
__device__ __forceinline__ void emit_one(
    unsigned mw, int packed, int incl, int cnt, int lane,
    float xi, float yi, float zi,
    const float* __restrict__ sx, const float* __restrict__ sy,
    const float* __restrict__ sz,
    int joff, int gi, int goff, int base,
    float* __restrict__ o_src, float* __restrict__ o_tgt,
    float* __restrict__ o_m,   float* __restrict__ o_d)
{
    const unsigned full = 0xffffffffu;
    bool usev = (lane < cnt);
    int r = usev ? lane : (lane - cnt);
    int lo = 0;
#pragma unroll
    for (int s = (W > 8 ? 16 : 4); s >= 1; s >>= 1) {
        int probe = lo + s;
        int src = (probe < W ? probe : W) - 1;
        int pvp = __shfl_sync(full, incl, src);
        int pv  = (pvp >> SH) & 0xffff;
        int pvu = usev ? pv : ((probe << 5) - pv);
        if (probe < W && pvu <= r) lo = probe;
    }
    int inclp = __shfl_sync(full, incl, lo);
    int pcp   = __shfl_sync(full, packed, lo);
    int incl_lo = (inclp >> SH) & 0xffff;
    int pc_lo   = (pcp  >> SH) & 0xffff;
    int excl_v  = incl_lo - pc_lo;
    int exclu   = usev ? excl_v : ((lo << 5) - excl_v);
    int rin     = r - exclu;
    unsigned mwlo = __shfl_sync(full, mw, lo);
    unsigned msel = usev ? mwlo : ~mwlo;
    int bit = nth_set_bit(msel, rin + 1);
    int j = joff + (lo << 5) + bit;                      // batch-local index
    int fi = fidx_of(j);
    float dx = xi + sx[fi], dy = yi + sy[fi], dz = zi + sz[fi]; // coords negated
    float d2 = fmaf(dx, dx, fmaf(dy, dy, dz * dz));      // same chain as scan
    o_src[base] = (float)(goff + j);
    o_tgt[base] = (float)(goff + gi);
    o_m[base]   = usev ? 1.0f : 0.0f;
    o_d[base]   = usev ? sqrt_approx(d2) : 0.0f;
}

// joint A/B selection: one packed (A | B<<16) prefix scan serves both targets
template<int W>
__device__ __forceinline__ void select_pair(
    unsigned mwA, unsigned mwB, int lane,
    float xA, float yA, float zA, float xB, float yB, float zB,
    const float* __restrict__ sx, const float* __restrict__ sy,
    const float* __restrict__ sz,
    int joff, int iA, int iB, int goff, int baseA, int baseB,
    float* __restrict__ o_src, float* __restrict__ o_tgt,
    float* __restrict__ o_m,   float* __restrict__ o_d)
{
    const unsigned full = 0xffffffffu;
    int packed = __popc(mwA) | (__popc(mwB) << 16);
    int incl = packed;
#pragma unroll
    for (int d = 1; d < (W > 8 ? 32 : 8); d <<= 1) {
        int n = __shfl_up_sync(full, incl, d);
        if (lane >= d) incl += n;
    }
    int cntP = __shfl_sync(full, incl, W - 1);
    emit_one<W, 0>(mwA, packed, incl, cntP & 0xffff, lane, xA, yA, zA,
                   sx, sy, sz, joff, iA, goff, baseA, o_src, o_tgt, o_m, o_d);
    emit_one<W, 16>(mwB, packed, incl, cntP >> 16, lane, xB, yB, zB,
                    sx, sy, sz, joff, iB, goff, baseB, o_src, o_tgt, o_m, o_d);
}

__global__ void __launch_bounds__(TPB_, 3)
mo3enet_knn_fns_kernel(const float* __restrict__ pos, float* __restrict__ out) {
    __shared__ ulonglong2 snx4[PER_ / 4];       // 4 KB  negated x, quad-packed
    __shared__ ulonglong2 sny4[PER_ / 4];       // 4 KB
    __shared__ ulonglong2 snz4[PER_ / 4];       // 4 KB
    __shared__ unsigned   smA[WPB_][32];        // 2 KB  masks, word w = cands [32w,32w+32)
    __shared__ unsigned   smB[WPB_][32];        // 2 KB

    const int b    = blockIdx.x / BPB_;
    const int grp  = blockIdx.x % BPB_;
    const int tid  = threadIdx.x;
    const int warp = tid >> 5;
    const int lane = tid & 31;
    const unsigned full = 0xffffffffu;

    const float* sx = (const float*)snx4;
    const float* sy = (const float*)sny4;
    const float* sz = (const float*)snz4;

    // ---- stage batch positions (negated) into quad-packed SoA ----
    const float* p = pos + (size_t)b * PER_ * 3;
    for (int j = tid; j < PER_; j += TPB_) {
        int fi = fidx_of(j);
        ((float*)snx4)[fi] = -p[3 * j + 0];
        ((float*)sny4)[fi] = -p[3 * j + 1];
        ((float*)snz4)[fi] = -p[3 * j + 2];
    }
    __syncthreads();

    // this warp's two targets
    const int iA = grp * TGT_PER_BLOCK + warp * 2;
    const int iB = iA + 1;
    const int goff = b * PER_;

    float xA, yA, zA, xB, yB, zB;
    {
        int fa = fidx_of(iA);
        xA = -sx[fa]; yA = -sy[fa]; zA = -sz[fa];
        int fb = fidx_of(iB);
        xB = -sx[fb]; yB = -sy[fb]; zB = -sz[fb];
    }
    const u64 xA2 = pack2(xA, xA), yA2 = pack2(yA, yA), zA2 = pack2(zA, zA);
    const u64 xB2 = pack2(xB, xB), yB2 = pack2(yB, yB), zB2 = pack2(zB, zB);

    const int baseA = (b * NIN_ + iA) * K_ + lane;
    const int baseB = (b * NIN_ + iB) * K_ + lane;

    // ---- scan macro body for one 128-candidate tile t ----
#define SCAN_TILE(t)                                                          \
    {                                                                         \
        ulonglong2 qx = snx4[(t) * 32 + lane];                                \
        ulonglong2 qy = sny4[(t) * 32 + lane];                                \
        ulonglong2 qz = snz4[(t) * 32 + lane];                                \
        {                                                                     \
            u64 dxl = add2(xA2, qx.x), dxh = add2(xA2, qx.y);                 \
            u64 dyl = add2(yA2, qy.x), dyh = add2(yA2, qy.y);                 \
            u64 dzl = add2(zA2, qz.x), dzh = add2(zA2, qz.y);                 \
            u64 sl = fma2(dxl, dxl, fma2(dyl, dyl, mul2(dzl, dzl)));          \
            u64 sh = fma2(dxh, dxh, fma2(dyh, dyh, mul2(dzh, dzh)));          \
            float f0, f1, f2, f3; unpack2(sl, f0, f1); unpack2(sh, f2, f3);   \
            uint4 m;                                                          \
            m.x = __ballot_sync(full, f0 < 36.0f);                            \
            m.y = __ballot_sync(full, f1 < 36.0f);                            \
            m.z = __ballot_sync(full, f2 < 36.0f);                            \
            m.w = __ballot_sync(full, f3 < 36.0f);                            \
            if (lane == 0) *(uint4*)&smA[warp][4 * (t)] = m;                  \
        }                                                                     \
        {                                                                     \
            u64 dxl = add2(xB2, qx.x), dxh = add2(xB2, qx.y);                 \
            u64 dyl = add2(yB2, qy.x), dyh = add2(yB2, qy.y);                 \
            u64 dzl = add2(zB2, qz.x), dzh = add2(zB2, qz.y);                 \
            u64 sl = fma2(dxl, dxl, fma2(dyl, dyl, mul2(dzl, dzl)));          \
            u64 sh = fma2(dxh, dxh, fma2(dyh, dyh, mul2(dzh, dzh)));          \
            float f0, f1, f2, f3; unpack2(sl, f0, f1); unpack2(sh, f2, f3);   \
            uint4 m;                                                          \
            m.x = __ballot_sync(full, f0 < 36.0f);                            \
            m.y = __ballot_sync(full, f1 < 36.0f);                            \
            m.z = __ballot_sync(full, f2 < 36.0f);                            \
            m.w = __ballot_sync(full, f3 < 36.0f);                            \
            if (lane == 0) *(uint4*)&smB[warp][4 * (t)] = m;                  \
        }                                                                     \
    }

    // ===== phase 1: ii tiles (candidates 0..255 = words 0..7) ================
    SCAN_TILE(0)
    SCAN_TILE(1)
    __syncwarp();

    // ===== phase 2: io scan (tiles 2..7) + ii selection ======================
    {
        unsigned mwA = smA[warp][lane];
        unsigned mwB = smB[warp][lane];
        // clear self bit (d2(i,i)=0<36 set it); word index = i>>5 in [0,8)
        if (lane == (iA >> 5)) mwA &= ~(1u << (iA & 31));
        if (lane == (iB >> 5)) mwB &= ~(1u << (iB & 31));

        SCAN_TILE(2)
        SCAN_TILE(3)
        SCAN_TILE(4)
        SCAN_TILE(5)
        SCAN_TILE(6)
        SCAN_TILE(7)

        select_pair<NIN_ / 32>(mwA, mwB, lane, xA, yA, zA, xB, yB, zB,
                               sx, sy, sz, 0, iA, iB, goff, baseA, baseB,
                               out + 0 * E_, out + 1 * E_, out + 2 * E_, out + 3 * E_);
    }
    __syncwarp();

    // ===== phase 3: io selection (words 8..31, W=24) =========================
    {
        int wl = (8 + lane) & 31;     // lanes 24..31 wrap in-bounds (unused)
        unsigned mwA = smA[warp][wl];
        unsigned mwB = smB[warp][wl];
        select_pair<NOUT_ / 32>(mwA, mwB, lane, xA, yA, zA, xB, yB, zB,
                                sx, sy, sz, NIN_, iA, iB, goff, baseA, baseB,
                                out + 4 * E_, out + 5 * E_, out + 6 * E_, out + 7 * E_);
    }
#undef SCAN_TILE
}

extern "C" void kernel_launch(void* const* d_in, const int* in_sizes, int n_in,
                              void* d_out, int out_size) {
    const float* pos = (const float*)d_in[0];   // [N, 3] float32
    float* out = (float*)d_out;
    mo3enet_knn_fns_kernel<<<GRID_, TPB_>>>(pos, out);
}

// round 15
// speedup vs baseline: 1.0511x; 1.0397x over previous
#include <cuda_runtime.h>

// Problem constants (match reference_code)
#define B_    256
#define PER_  1024
#define NIN_  256
#define NOUT_ (PER_ - NIN_)
#define K_    32
#define E_    (B_ * NIN_ * K_)      // 2,097,152

#define TPB_  512
#define WPB_  16                     // warps per block
#define TGT_PER_BLOCK 32             // 2 targets per warp
#define BPB_  (NIN_ / TGT_PER_BLOCK) // 8 blocks per batch
#define GRID_ (B_ * BPB_)            // 2048

typedef unsigned long long u64;

// ---- packed f32x2 helpers ----
__device__ __forceinline__ u64 pack2(float lo, float hi) {
    u64 r; asm("mov.b64 %0, {%1, %2};" : "=l"(r) : "f"(lo), "f"(hi)); return r;
}
__device__ __forceinline__ void unpack2(u64 v, float& lo, float& hi) {
    asm("mov.b64 {%0, %1}, %2;" : "=f"(lo), "=f"(hi) : "l"(v));
}
__device__ __forceinline__ u64 add2(u64 a, u64 b) {
    u64 r; asm("add.rn.f32x2 %0, %1, %2;" : "=l"(r) : "l"(a), "l"(b)); return r;
}
__device__ __forceinline__ u64 mul2(u64 a, u64 b) {
    u64 r; asm("mul.rn.f32x2 %0, %1, %2;" : "=l"(r) : "l"(a), "l"(b)); return r;
}
__device__ __forceinline__ u64 fma2(u64 a, u64 b, u64 c) {
    u64 r; asm("fma.rn.f32x2 %0, %1, %2, %3;" : "=l"(r) : "l"(a), "l"(b), "l"(c)); return r;
}
__device__ __forceinline__ float sqrt_approx(float x) {
    float r; asm("sqrt.approx.f32 %0, %1;" : "=f"(r) : "f"(x)); return r;
}

// Branchless (need)-th-set-bit finder: 5-step popc binary search (~25 fixed-lat
// ALU ops). Precondition: m has at least `need` set bits (1-based).
__device__ __forceinline__ int nth_set_bit(unsigned m, int need) {
    int pos = 0;
    int c = __popc(m & 0xffffu);
    if (c < need) { need -= c; pos = 16; }
    c = __popc((m >> pos) & 0xffu);
    if (c < need) { need -= c; pos += 8; }
    c = __popc((m >> pos) & 0xfu);
    if (c < need) { need -= c; pos += 4; }
    c = __popc((m >> pos) & 0x3u);
    if (c < need) { need -= c; pos += 2; }
    c = (m >> pos) & 1u;
    if (c < need) { pos += 1; }
    return pos;
}

// Quad-packed smem layout: float index of candidate j (bit permutation):
//   fidx = ((j>>7)<<7) | ((j&31)<<2) | ((j>>5)&3)
__device__ __forceinline__ int fidx_of(int j) {
    return ((j >> 7) << 7) | ((j & 31) << 2) | ((j >> 5) & 3);
}

// validity: d = sqrt(d2) < 6  <=>  d2 < 36 (monotone sqrt, sqrt(36)=6 exact)

// ---- rank selection for one target in one word-region [LO, HI) ------------
// mw     : this lane's mask word (lane = GLOBAL word index; region words only)
// packed : popcA | popcB<<16 for this lane's word
// incl   : inclusive packed prefix over ALL 32 words
// cnt    : region valid count for this target; exb: incl at word LO-1 (field)
// Output slot `lane`: lane-th valid cand if lane<cnt else (lane-cnt)-th invalid.
// All shuffles executed unconditionally by all lanes (divergence-fix invariant).
template<int LO, int HI, int SH>
__device__ __forceinline__ void emit_one(
    unsigned mw, int packed, int incl, int cnt, int exb, int lane,
    float xi, float yi, float zi,
    const float* __restrict__ sx, const float* __restrict__ sy,
    const float* __restrict__ sz,
    int gi, int goff, int base,
    float* __restrict__ o_src, float* __restrict__ o_tgt,
    float* __restrict__ o_m,   float* __restrict__ o_d)
{
    const unsigned full = 0xffffffffu;
    bool usev = (lane < cnt);
    int r = usev ? lane : (lane - cnt);
    int lo = LO;
#pragma unroll
    for (int s = ((HI - LO) > 8 ? 16 : 4); s >= 1; s >>= 1) {
        int probe = lo + s;
        int src = (probe < HI ? probe : HI) - 1;
        int pvp = __shfl_sync(full, incl, src);
        int pv  = ((pvp >> SH) & 0xffff) - exb;          // region-local valid excl
        int pvu = usev ? pv : (((probe - LO) << 5) - pv);
        if (probe < HI && pvu <= r) lo = probe;
    }
    int inclp = __shfl_sync(full, incl, lo);
    int pcp   = __shfl_sync(full, packed, lo);
    int incl_lo = ((inclp >> SH) & 0xffff) - exb;
    int pc_lo   = (pcp  >> SH) & 0xffff;
    int excl_v  = incl_lo - pc_lo;
    int exclu   = usev ? excl_v : (((lo - LO) << 5) - excl_v);
    int rin     = r - exclu;
    unsigned mwlo = __shfl_sync(full, mw, lo);
    unsigned msel = usev ? mwlo : ~mwlo;
    int bit = nth_set_bit(msel, rin + 1);
    int j = (lo << 5) + bit;                 // word index is GLOBAL: j direct
    int fi = fidx_of(j);
    float dx = xi + sx[fi], dy = yi + sy[fi], dz = zi + sz[fi]; // coords negated
    float d2 = fmaf(dx, dx, fmaf(dy, dy, dz * dz));      // same chain as scan
    o_src[base] = (float)(goff + j);
    o_tgt[base] = (float)(goff + gi);
    o_m[base]   = usev ? 1.0f : 0.0f;
    o_d[base]   = usev ? sqrt_approx(d2) : 0.0f;
}

__global__ void __launch_bounds__(TPB_, 3)
mo3enet_knn_m_kernel(const float* __restrict__ pos, float* __restrict__ out) {
    __shared__ ulonglong2 snx4[PER_ / 4];       // 4 KB  negated x, quad-packed
    __shared__ ulonglong2 sny4[PER_ / 4];       // 4 KB
    __shared__ ulonglong2 snz4[PER_ / 4];       // 4 KB
    __shared__ unsigned   smA[WPB_][32];        // 2 KB  masks, word w = cands [32w,32w+32)
    __shared__ unsigned   smB[WPB_][32];        // 2 KB

    const int b    = blockIdx.x / BPB_;
    const int grp  = blockIdx.x % BPB_;
    const int tid  = threadIdx.x;
    const int warp = tid >> 5;
    const int lane = tid & 31;
    const unsigned full = 0xffffffffu;

    const float* sx = (const float*)snx4;
    const float* sy = (const float*)sny4;
    const float* sz = (const float*)snz4;

    // ---- stage batch positions (negated) into quad-packed SoA ----
    const float* p = pos + (size_t)b * PER_ * 3;
    for (int j = tid; j < PER_; j += TPB_) {
        int fi = fidx_of(j);
        ((float*)snx4)[fi] = -p[3 * j + 0];
        ((float*)sny4)[fi] = -p[3 * j + 1];
        ((float*)snz4)[fi] = -p[3 * j + 2];
    }
    __syncthreads();

    // this warp's two targets
    const int iA = grp * TGT_PER_BLOCK + warp * 2;
    const int iB = iA + 1;
    const int goff = b * PER_;

    float xA, yA, zA, xB, yB, zB;
    {
        int fa = fidx_of(iA);
        xA = -sx[fa]; yA = -sy[fa]; zA = -sz[fa];
        int fb = fidx_of(iB);
        xB = -sx[fb]; yB = -sy[fb]; zB = -sz[fb];
    }
    const u64 xA2 = pack2(xA, xA), yA2 = pack2(yA, yA), zA2 = pack2(zA, zA);
    const u64 xB2 = pack2(xB, xB), yB2 = pack2(yB, yB), zB2 = pack2(zB, zB);

    const int baseA = (b * NIN_ + iA) * K_ + lane;
    const int baseB = (b * NIN_ + iB) * K_ + lane;

    // ==================== unified scan: 8 tiles of 128 candidates ============
#pragma unroll
    for (int t = 0; t < PER_ / 128; t++) {
        ulonglong2 qx = snx4[t * 32 + lane];
        ulonglong2 qy = sny4[t * 32 + lane];
        ulonglong2 qz = snz4[t * 32 + lane];
        {
            u64 dxl = add2(xA2, qx.x), dxh = add2(xA2, qx.y);
            u64 dyl = add2(yA2, qy.x), dyh = add2(yA2, qy.y);
            u64 dzl = add2(zA2, qz.x), dzh = add2(zA2, qz.y);
            u64 sl = fma2(dxl, dxl, fma2(dyl, dyl, mul2(dzl, dzl)));
            u64 sh = fma2(dxh, dxh, fma2(dyh, dyh, mul2(dzh, dzh)));
            float f0, f1, f2, f3; unpack2(sl, f0, f1); unpack2(sh, f2, f3);
            uint4 m;
            m.x = __ballot_sync(full, f0 < 36.0f);
            m.y = __ballot_sync(full, f1 < 36.0f);
            m.z = __ballot_sync(full, f2 < 36.0f);
            m.w = __ballot_sync(full, f3 < 36.0f);
            if (lane == 0) *(uint4*)&smA[warp][4 * t] = m;
        }
        {
            u64 dxl = add2(xB2, qx.x), dxh = add2(xB2, qx.y);
            u64 dyl = add2(yB2, qy.x), dyh = add2(yB2, qy.y);
            u64 dzl = add2(zB2, qz.x), dzh = add2(zB2, qz.y);
            u64 sl = fma2(dxl, dxl, fma2(dyl, dyl, mul2(dzl, dzl)));
            u64 sh = fma2(dxh, dxh, fma2(dyh, dyh, mul2(dzh, dzh)));
            float f0, f1, f2, f3; unpack2(sl, f0, f1); unpack2(sh, f2, f3);
            uint4 m;
            m.x = __ballot_sync(full, f0 < 36.0f);
            m.y = __ballot_sync(full, f1 < 36.0f);
            m.z = __ballot_sync(full, f2 < 36.0f);
            m.w = __ballot_sync(full, f3 < 36.0f);
            if (lane == 0) *(uint4*)&smB[warp][4 * t] = m;
        }
    }
    __syncwarp();

    // ==================== merged selection: ONE 32-word prefix scan ==========
    {
        unsigned mwA = smA[warp][lane];
        unsigned mwB = smB[warp][lane];
        // clear self bit (d2(i,i)=0<36 set it); word index = i>>5 in [0,8)
        if (lane == (iA >> 5)) mwA &= ~(1u << (iA & 31));
        if (lane == (iB >> 5)) mwB &= ~(1u << (iB & 31));

        int packed = __popc(mwA) | (__popc(mwB) << 16);
        int incl = packed;
#pragma unroll
        for (int d = 1; d < 32; d <<= 1) {
            int n = __shfl_up_sync(full, incl, d);
            if (lane >= d) incl += n;
        }
        int incl7  = __shfl_sync(full, incl, 7);    // end of ii region (words 0..7)
        int incl31 = __shfl_sync(full, incl, 31);   // end of io region (words 8..31)

        int cntiiA = incl7 & 0xffff,  cntiiB = incl7 >> 16;
        int cntioA = (incl31 & 0xffff) - cntiiA;
        int cntioB = (incl31 >> 16)   - cntiiB;

        // ii (words 0..7): exb = 0
        emit_one<0, 8, 0>(mwA, packed, incl, cntiiA, 0, lane, xA, yA, zA,
                          sx, sy, sz, iA, goff, baseA,
                          out + 0 * E_, out + 1 * E_, out + 2 * E_, out + 3 * E_);
        emit_one<0, 8, 16>(mwB, packed, incl, cntiiB, 0, lane, xB, yB, zB,
                           sx, sy, sz, iB, goff, baseB,
                           out + 0 * E_, out + 1 * E_, out + 2 * E_, out + 3 * E_);
        // io (words 8..31): exb = incl at word 7 (per-target field)
        emit_one<8, 32, 0>(mwA, packed, incl, cntioA, cntiiA, lane, xA, yA, zA,
                           sx, sy, sz, iA, goff, baseA,
                           out + 4 * E_, out + 5 * E_, out + 6 * E_, out + 7 * E_);
        emit_one<8, 32, 16>(mwB, packed, incl, cntioB, cntiiB, lane, xB, yB, zB,
                            sx, sy, sz, iB, goff, baseB,
                            out + 4 * E_, out + 5 * E_, out + 6 * E_, out + 7 * E_);
    }
}

extern "C" void kernel_launch(void* const* d_in, const int* in_sizes, int n_in,
                              void* d_out, int out_size) {
    const float* pos = (const float*)d_in[0];   // [N, 3] float32
    float* out = (float*)d_out;
    mo3enet_knn_m_kernel<<<GRID_, TPB_>>>(pos, out);
}